// round 13
// baseline (speedup 1.0000x reference)
#include <cuda_runtime.h>
#include <cstdint>

// ---------------------------------------------------------------------------
// Problem constants
//   B=128, T_V=64, T_A=128, E_V=1024, E_A=512, H=1024, EMB=512, C=512
//   IN=1024, VOCAB=20000
// Output = [logits(128*20000) | h_new(128*1024) | c_new(128*1024)]
// ---------------------------------------------------------------------------

// Scratch offsets (floats)
#define OFF_V2V     0u            // 8192*512
#define OFF_V2A     4194304u      // 16384*512
#define OFF_V1V     12582912u     // 128*512
#define OFF_V1A     12648448u     // 128*512
#define OFF_V1C     12713984u     // 128*512
#define OFF_CTXV    12779520u     // 128*1024
#define OFF_CTXA    12910592u     // 128*512
#define OFF_ALLCTX  12976128u     // 128*2*512
#define OFF_V2C     13107200u     // 256*512
#define OFF_X2      13238272u     // 128*512
#define OFF_GATES   13369344u     // 128*4096
#define OFF_H       13893632u     // 128*1024
#define OFF_VTMP    14024704u     // 128*512
#define OFF_V2CTMP  14090240u     // 256*512
#define OFF_GATES2  14221312u     // 128*4096
#define SCRATCH_FLOATS 14745600u

__device__ float g_scratch[SCRATCH_FLOATS];
__device__ int g_bar[8];   // monotonic barrier counters (never reset; replay-safe)

__device__ __forceinline__ uint32_t f2tf(float f) {
    uint32_t u;
    asm("cvt.rna.tf32.f32 %0, %1;" : "=r"(u) : "f"(f));
    return u;
}
__device__ __forceinline__ float f2tf_f(float f) {
    return __uint_as_float(f2tf(f));
}

// Grid-wide barrier for a co-resident grid of nblk blocks. Tight spin.
__device__ __forceinline__ void grid_bar(int i, int nblk) {
    __syncthreads();
    if (threadIdx.x == 0) {
        __threadfence();
        int old = atomicAdd(&g_bar[i], 1);
        int goal = (old / nblk + 1) * nblk;
        volatile int* p = &g_bar[i];
        while (*p < goal) { }
        __threadfence();
    }
    __syncthreads();
}

// ---------------------------------------------------------------------------
// Async TF32 core, FAT tile: 128(M) x 64(N) x 32(K), 128 threads, 4 warps
// as 2x2, warp tile 64x32. cp.async 2-stage + XOR-swizzled smem + ldmatrix.
// aRd: A operand is already tf32-rna-rounded by its producer -> skip A cvt
// (bitwise-identical numerics; rounding applied exactly once either way).
// M%128==0, K%32==0, lda/ldb%4==0. N ragged OK (B rows clamped; epilogue
// guarded).
// smem sm[12288] uint32 = 48KB:
//   A stage0 @ byte 0, A stage1 @ 16384 ; B stage0 @ 32768, B stage1 @ 40960.
//   Row r: 16B group g stored at physical group g ^ (r & 7).
// ---------------------------------------------------------------------------
__device__ __forceinline__ void cp16(uint32_t dst, const float* src) {
    asm volatile("cp.async.ca.shared.global [%0], [%1], 16;"
                 :: "r"(dst), "l"(src));
}
__device__ __forceinline__ void cp_commit() {
    asm volatile("cp.async.commit_group;");
}
__device__ __forceinline__ void ldsm4(uint32_t* r, uint32_t addr) {
    asm volatile("ldmatrix.sync.aligned.m8n8.x4.shared.b16 {%0,%1,%2,%3}, [%4];"
                 : "=r"(r[0]), "=r"(r[1]), "=r"(r[2]), "=r"(r[3]) : "r"(addr));
}

__device__ __forceinline__ void gemm_async_core(
    const float* __restrict__ A, int lda,
    const float* __restrict__ B, int ldb,
    const float* __restrict__ bias,
    float* __restrict__ C, int ldc,
    int N, int K, int accum, int mBase, int nBase,
    int aRd, uint32_t* sm)
{
    const int tid  = threadIdx.x;
    const int lane = tid & 31;
    const int warp = tid >> 5;
    const int wm = warp >> 1;
    const int wn = warp & 1;
    const int lr = tid >> 3;
    const int lc = tid & 7;
    const int nk = K >> 5;

    const uint32_t smBase = (uint32_t)__cvta_generic_to_shared(sm);
    const int sg = lc ^ (lr & 7);
    const float* aS0 = A + (size_t)(mBase + lr) * lda + (lc << 2);
    const size_t strideA16 = (size_t)16 * lda;
    const float* bS[4];
#pragma unroll
    for (int i = 0; i < 4; i++) {
        int nr = nBase + lr + i * 16;
        if (nr > N - 1) nr = N - 1;
        bS[i] = B + (size_t)nr * ldb + (lc << 2);
    }
    const uint32_t aD = smBase + lr * 128 + sg * 16;
    const uint32_t bD = smBase + 32768 + lr * 128 + sg * 16;

    auto issue = [&](int kt, int st) {
        const int ko = kt << 5;
        const uint32_t soA = st ? 16384u : 0u;
        const uint32_t soB = st ? 8192u : 0u;
#pragma unroll
        for (int i = 0; i < 8; i++)
            cp16(aD + (uint32_t)i * 2048u + soA, aS0 + (size_t)i * strideA16 + ko);
#pragma unroll
        for (int i = 0; i < 4; i++)
            cp16(bD + (uint32_t)i * 2048u + soB, bS[i] + ko);
        cp_commit();
    };

    float acc[4][4][4];
#pragma unroll
    for (int i = 0; i < 4; i++)
#pragma unroll
        for (int j = 0; j < 4; j++)
#pragma unroll
            for (int k = 0; k < 4; k++) acc[i][j][k] = 0.f;

    issue(0, 0);
    if (nk > 1) issue(1, 1);

    const int l7 = lane & 7;
    const int q3 = (lane >> 3) & 1;
    const int q4 = (lane >> 4) & 1;
    const uint32_t aAB = smBase + ((wm << 6) + l7 + (q3 << 3)) * 128;
    const uint32_t bAB = smBase + 32768 + ((wn << 5) + l7 + (q4 << 3)) * 128;

    for (int kt = 0; kt < nk; kt++) {
        if (kt < nk - 1) asm volatile("cp.async.wait_group 1;");
        else             asm volatile("cp.async.wait_group 0;");
        __syncthreads();

        const int st = kt & 1;
        const uint32_t swA = st ? 16384u : 0u;
        const uint32_t swB = st ? 8192u : 0u;
#pragma unroll
        for (int kk = 0; kk < 32; kk += 8) {
            const int kk4 = kk >> 2;
            uint32_t am[4][4], bm[2][4];
            const uint32_t ag = (uint32_t)((kk4 + q4) ^ l7);
            const uint32_t aaddr = aAB + swA + ag * 16;
            ldsm4(am[0], aaddr);
            ldsm4(am[1], aaddr + 2048);
            ldsm4(am[2], aaddr + 4096);
            ldsm4(am[3], aaddr + 6144);
            const uint32_t bg = (uint32_t)((kk4 + q3) ^ l7);
            const uint32_t baddr = bAB + swB + bg * 16;
            ldsm4(bm[0], baddr);
            ldsm4(bm[1], baddr + 2048);

            if (!aRd) {
#pragma unroll
                for (int im = 0; im < 4; im++)
#pragma unroll
                    for (int j = 0; j < 4; j++)
                        am[im][j] = f2tf(__uint_as_float(am[im][j]));
            }
#pragma unroll
            for (int p = 0; p < 2; p++)
#pragma unroll
                for (int j = 0; j < 4; j++)
                    bm[p][j] = f2tf(__uint_as_float(bm[p][j]));

#pragma unroll
            for (int im = 0; im < 4; im++)
#pragma unroll
                for (int jn = 0; jn < 4; jn++) {
                    const uint32_t b0 = bm[jn >> 1][(jn & 1) << 1];
                    const uint32_t b1 = bm[jn >> 1][((jn & 1) << 1) + 1];
                    asm volatile(
                        "mma.sync.aligned.m16n8k8.row.col.f32.tf32.tf32.f32 "
                        "{%0,%1,%2,%3}, {%4,%5,%6,%7}, {%8,%9}, {%0,%1,%2,%3};"
                        : "+f"(acc[im][jn][0]), "+f"(acc[im][jn][1]),
                          "+f"(acc[im][jn][2]), "+f"(acc[im][jn][3])
                        : "r"(am[im][0]), "r"(am[im][1]), "r"(am[im][2]), "r"(am[im][3]),
                          "r"(b0), "r"(b1));
                }
        }

        __syncthreads();
        if (kt + 2 < nk) issue(kt + 2, kt & 1);
    }

#pragma unroll
    for (int im = 0; im < 4; im++) {
        const int m0 = mBase + (wm << 6) + (im << 4) + (lane >> 2);
#pragma unroll
        for (int jn = 0; jn < 4; jn++) {
            const int n0 = nBase + (wn << 5) + (jn << 3) + ((lane & 3) << 1);
#pragma unroll
            for (int half = 0; half < 2; half++) {
                const int m = m0 + half * 8;
                const float v0 = acc[im][jn][half * 2 + 0];
                const float v1 = acc[im][jn][half * 2 + 1];
                if (n0 < N) {
                    float xv = v0 + (bias ? bias[n0] : 0.f);
                    if (accum) C[(size_t)m * ldc + n0] += xv;
                    else       C[(size_t)m * ldc + n0]  = xv;
                }
                if (n0 + 1 < N) {
                    float xv = v1 + (bias ? bias[n0 + 1] : 0.f);
                    if (accum) C[(size_t)m * ldc + n0 + 1] += xv;
                    else       C[(size_t)m * ldc + n0 + 1]  = xv;
                }
            }
        }
    }
}

struct GemmGroup {
    const float* A; const float* B; const float* bias; float* C;
    int lda, ldb, ldc, N, K, accum, aRd, nbx, end;
};
struct GemmList { GemmGroup g[8]; int n; };

__global__ void __launch_bounds__(128) gemm_async_grouped(GemmList L)
{
    __shared__ uint32_t sm[12288];   // 48KB exactly

    const int bid = blockIdx.x;
    int gi = 0;
#pragma unroll
    for (int i = 0; i < 8; i++)
        if (i < L.n && bid >= L.g[i].end) gi = i + 1;
    const GemmGroup& G = L.g[gi];
    const int start = gi ? L.g[gi - 1].end : 0;
    const int lb = bid - start;
    const int by = lb / G.nbx;
    const int bx = lb - by * G.nbx;

    gemm_async_core(G.A, G.lda, G.B, G.ldb, G.bias, G.C, G.ldc,
                    G.N, G.K, G.accum, by << 7, bx << 6, G.aRd, sm);
}

// ---------------------------------------------------------------------------
// Both Bahdanau attentions in one launch. ctx written tf32-rna-rounded
// (consumed ONLY as GEMM A-operand in the chain -> bitwise-identical).
// ---------------------------------------------------------------------------
struct AttParams {
    const float* v1; const float* v2; const float* W3; const float* enc;
    float* ctx; int T, C, E;
};

__global__ void __launch_bounds__(256) attend_both(AttParams P0, AttParams P1)
{
    const AttParams P = (blockIdx.x >> 7) ? P1 : P0;
    const int b = blockIdx.x & 127;
    const int tid = threadIdx.x;
    const int warp = tid >> 5, lane = tid & 31;
    __shared__ float s_sc[128];
    __shared__ float s_inv;

    const int T = P.T, C = P.C, E = P.E;
    const float* v1b = P.v1 + (size_t)b * C;
    const float* v2b = P.v2 + (size_t)b * T * C;

    for (int t = warp; t < T; t += 8) {
        const float* row = v2b + (size_t)t * C;
        float acc = 0.f;
        for (int c = lane; c < C; c += 32)
            acc += tanhf(v1b[c] + row[c]) * P.W3[c];
#pragma unroll
        for (int o = 16; o; o >>= 1) acc += __shfl_xor_sync(0xffffffffu, acc, o);
        if (lane == 0) s_sc[t] = acc;
    }
    __syncthreads();

    if (tid == 0) {
        float m = -1e30f;
        for (int t = 0; t < T; t++) m = fmaxf(m, s_sc[t]);
        float s = 0.f;
        for (int t = 0; t < T; t++) { float e = expf(s_sc[t] - m); s_sc[t] = e; s += e; }
        s_inv = 1.f / s;
    }
    __syncthreads();
    const float inv = s_inv;

    const float* encb = P.enc + (size_t)b * T * E;
    for (int e = tid; e < E; e += 256) {
        float acc = 0.f;
        for (int t = 0; t < T; t++) acc += s_sc[t] * encb[(size_t)t * E + e];
        P.ctx[(size_t)b * E + e] = f2tf_f(acc * inv);
    }
}

// ---------------------------------------------------------------------------
// Persistent fused chain with split-K parallelism (128x64 tile tasks).
// Grid MUST be 128 blocks x 128 threads (co-resident; tight-spin barriers).
// ---------------------------------------------------------------------------
struct ChainParams {
    const float* ctxv; const float* ctxa;
    const float* W_venc; const float* W_aenc; const float* W_ca2;
    const float* v1c; const float* W_ca3; const float* W_ih;
    const float* b_ih; const float* b_hh; const float* c0;
    float* allctx; float* vtmp; float* v2c; float* v2ctmp;
    float* x2; float* gates; const float* gates2;
    float* hsc; float* h_out; float* c_out;
};

__global__ void __launch_bounds__(128) fused_chain(ChainParams P)
{
    __shared__ uint32_t sm[12288];
    float* redf = (float*)sm;

    const int bid = blockIdx.x;
    const int tid = threadIdx.x;

    // ---- P1: proj (A = ctx, pre-rounded -> aRd=1) ----
    if (bid < 24) {
        if (bid < 8) {
            gemm_async_core(P.ctxv, 1024, P.W_venc, 1024, nullptr, P.allctx, 1024,
                            512, 512, 0, 0, bid << 6, 1, sm);
        } else if (bid < 16) {
            const int t = bid - 8;
            gemm_async_core(P.ctxv + 512, 1024, P.W_venc + 512, 1024, nullptr,
                            P.vtmp, 512, 512, 512, 0, 0, t << 6, 1, sm);
        } else {
            const int t = bid - 16;
            gemm_async_core(P.ctxa, 512, P.W_aenc, 512, nullptr, P.allctx + 512, 1024,
                            512, 512, 0, 0, t << 6, 1, sm);
        }
    }
    grid_bar(0, 128);

    // ---- P1b: reduce vis partials into allctx ----
    for (int u = bid * 128 + tid; u < 128 * 512; u += 128 * 128) {
        const int b = u >> 9, c = u & 511;
        P.allctx[(size_t)b * 1024 + c] += P.vtmp[u];
    }
    grid_bar(1, 128);

    // ---- P2: v2c[256,512] = allctx @ W_ca2^T, split-K=2 (A raw -> aRd=0) ----
    if (bid < 32) {
        const int kc = bid >> 4;
        const int t = bid & 15;
        const float* Aa = P.allctx + kc * 256;
        const float* Bb = P.W_ca2 + kc * 256;
        float* Cc = kc ? P.v2ctmp : P.v2c;
        gemm_async_core(Aa, 512, Bb, 512, nullptr, Cc, 512,
                        512, 256, 0, (t >> 3) << 7, (t & 7) << 6, 0, sm);
    }
    grid_bar(2, 128);

    // ---- P3: 2-way softmax + final ctx + x2 = tf32(tanh(final_ctx)) ----
    {
        const int b = bid;
        const int warp = tid >> 5, lane = tid & 31;
        const float* v1b  = P.v1c + (size_t)b * 512;
        const float* v20  = P.v2c + (size_t)(2 * b) * 512;
        const float* v21  = v20 + 512;
        const float* v20t = P.v2ctmp + (size_t)(2 * b) * 512;
        const float* v21t = v20t + 512;

        float p0 = 0.f, p1 = 0.f;
        for (int c = tid; c < 512; c += 128) {
            const float w = P.W_ca3[c];
            p0 += tanhf(v1b[c] + v20[c] + v20t[c]) * w;
            p1 += tanhf(v1b[c] + v21[c] + v21t[c]) * w;
        }
#pragma unroll
        for (int o = 16; o; o >>= 1) {
            p0 += __shfl_xor_sync(0xffffffffu, p0, o);
            p1 += __shfl_xor_sync(0xffffffffu, p1, o);
        }
        if (lane == 0) { redf[warp] = p0; redf[4 + warp] = p1; }
        __syncthreads();
        if (tid == 0) {
            float s0 = redf[0] + redf[1] + redf[2] + redf[3];
            float s1 = redf[4] + redf[5] + redf[6] + redf[7];
            const float m = fmaxf(s0, s1);
            const float e0 = expf(s0 - m), e1 = expf(s1 - m);
            const float inv = 1.f / (e0 + e1);
            redf[8] = e0 * inv; redf[9] = e1 * inv;
        }
        __syncthreads();
        const float a0 = redf[8], a1 = redf[9];

        const float* ctx0 = P.allctx + (size_t)b * 1024;
        const float* ctx1 = ctx0 + 512;
        float* xb = P.x2 + (size_t)b * 512;
        for (int c = tid; c < 512; c += 128)
            xb[c] = f2tf_f(tanhf(a0 * ctx0[c] + a1 * ctx1[c]));
        __syncthreads();
    }
    grid_bar(3, 128);

    // ---- P4: gates += x2 @ W_ih[:,512:]^T (x2 pre-rounded -> aRd=1) ----
    if (bid < 64) {
        gemm_async_core(P.x2, 512, P.W_ih + 512, 1024, nullptr, P.gates, 4096,
                        4096, 512, 1, 0, bid << 6, 1, sm);
    }
    grid_bar(4, 128);

    // ---- P5: LSTM pointwise; hsc stored tf32-rounded (logits A operand) ----
    for (int idx = bid * 128 + tid; idx < 128 * 1024; idx += 128 * 128) {
        const int b = idx >> 10, k = idx & 1023;
        const float* g  = P.gates  + (size_t)b * 4096;
        const float* g2 = P.gates2 + (size_t)b * 4096;
        const float ig = g[k]        + g2[k]        + P.b_ih[k]        + P.b_hh[k];
        const float fg = g[1024 + k] + g2[1024 + k] + P.b_ih[1024 + k] + P.b_hh[1024 + k];
        const float gg = g[2048 + k] + g2[2048 + k] + P.b_ih[2048 + k] + P.b_hh[2048 + k];
        const float og = g[3072 + k] + g2[3072 + k] + P.b_ih[3072 + k] + P.b_hh[3072 + k];

        const float si = 1.f / (1.f + expf(-ig));
        const float sf = 1.f / (1.f + expf(-fg));
        const float so = 1.f / (1.f + expf(-og));
        const float cn = sf * P.c0[idx] + si * tanhf(gg);
        const float hn = so * tanhf(cn);

        P.hsc[idx] = f2tf_f(hn);
        P.h_out[idx] = hn;
        P.c_out[idx] = cn;
    }
}

// ---------------------------------------------------------------------------
// Launch
// ---------------------------------------------------------------------------
static inline GemmGroup mkgrp(const float* A, int lda, const float* B, int ldb,
                              const float* bias, float* C, int ldc,
                              int M, int N, int K, int accum, int aRd, int prevEnd)
{
    GemmGroup g;
    g.A = A; g.B = B; g.bias = bias; g.C = C;
    g.lda = lda; g.ldb = ldb; g.ldc = ldc;
    g.N = N; g.K = K; g.accum = accum; g.aRd = aRd;
    g.nbx = (N + 63) / 64;
    g.end = prevEnd + g.nbx * (M / 128);
    return g;
}

extern "C" void kernel_launch(void* const* d_in, const int* in_sizes, int n_in,
                              void* d_out, int out_size)
{
    (void)in_sizes; (void)n_in; (void)out_size;

    float* S = nullptr;
    cudaGetSymbolAddress((void**)&S, g_scratch);

    const float* input  = (const float*)d_in[0];
    const float* enc_v  = (const float*)d_in[1];
    const float* enc_a  = (const float*)d_in[2];
    const float* h0     = (const float*)d_in[3];
    const float* c0     = (const float*)d_in[4];
    const float* W_va1  = (const float*)d_in[5];
    const float* W_va2  = (const float*)d_in[6];
    const float* W_va3  = (const float*)d_in[7];
    const float* W_venc = (const float*)d_in[8];
    const float* W_aa1  = (const float*)d_in[9];
    const float* W_aa2  = (const float*)d_in[10];
    const float* W_aa3  = (const float*)d_in[11];
    const float* W_aenc = (const float*)d_in[12];
    const float* W_ca1  = (const float*)d_in[13];
    const float* W_ca2  = (const float*)d_in[14];
    const float* W_ca3  = (const float*)d_in[15];
    const float* W_ih   = (const float*)d_in[16];
    const float* W_hh   = (const float*)d_in[17];
    const float* b_ih   = (const float*)d_in[18];
    const float* b_hh   = (const float*)d_in[19];
    const float* W_out  = (const float*)d_in[20];
    const float* b_out  = (const float*)d_in[21];

    float* out    = (float*)d_out;
    float* logits = out;
    float* h_out  = out + 128 * 20000;
    float* c_out  = h_out + 128 * 1024;

    float* v2v    = S + OFF_V2V;
    float* v2a    = S + OFF_V2A;
    float* v1v    = S + OFF_V1V;
    float* v1a    = S + OFF_V1A;
    float* v1c    = S + OFF_V1C;
    float* ctxv   = S + OFF_CTXV;
    float* ctxa   = S + OFF_CTXA;
    float* allctx = S + OFF_ALLCTX;
    float* v2c    = S + OFF_V2C;
    float* x2     = S + OFF_X2;
    float* gates  = S + OFF_GATES;
    float* hsc    = S + OFF_H;
    float* vtmp   = S + OFF_VTMP;
    float* v2ctmp = S + OFF_V2CTMP;
    float* gates2 = S + OFF_GATES2;

    // ---- launch 1: everything that depends only on inputs (fat async core) ----
    GemmList L1; L1.n = 7;
    L1.g[0] = mkgrp(enc_a, 512,  W_aa2, 512,  nullptr, v2a,    512,  16384, 512,  512,  0, 0, 0);
    L1.g[1] = mkgrp(enc_v, 1024, W_va2, 1024, nullptr, v2v,    512,  8192,  512,  1024, 0, 0, L1.g[0].end);
    L1.g[2] = mkgrp(h0,    1024, W_hh,  1024, nullptr, gates,  4096, 128,   4096, 1024, 0, 0, L1.g[1].end);
    L1.g[3] = mkgrp(input, 512,  W_ih,  1024, nullptr, gates2, 4096, 128,   4096, 512,  0, 0, L1.g[2].end);
    L1.g[4] = mkgrp(h0,    1024, W_va1, 1024, nullptr, v1v,    512,  128,   512,  1024, 0, 0, L1.g[3].end);
    L1.g[5] = mkgrp(h0,    1024, W_aa1, 1024, nullptr, v1a,    512,  128,   512,  1024, 0, 0, L1.g[4].end);
    L1.g[6] = mkgrp(h0,    1024, W_ca1, 1024, nullptr, v1c,    512,  128,   512,  1024, 0, 0, L1.g[5].end);
    gemm_async_grouped<<<L1.g[6].end, 128>>>(L1);

    // ---- launch 2: both attentions (ctx written tf32-rounded) ----
    AttParams Pv{v1v, v2v, W_va3, enc_v, ctxv, 64, 512, 1024};
    AttParams Pa{v1a, v2a, W_aa3, enc_a, ctxa, 128, 512, 512};
    attend_both<<<256, 256>>>(Pv, Pa);

    // ---- launch 3: persistent fused chain ----
    ChainParams CP;
    CP.ctxv = ctxv; CP.ctxa = ctxa;
    CP.W_venc = W_venc; CP.W_aenc = W_aenc; CP.W_ca2 = W_ca2;
    CP.v1c = v1c; CP.W_ca3 = W_ca3; CP.W_ih = W_ih;
    CP.b_ih = b_ih; CP.b_hh = b_hh; CP.c0 = c0;
    CP.allctx = allctx; CP.vtmp = vtmp; CP.v2c = v2c; CP.v2ctmp = v2ctmp;
    CP.x2 = x2; CP.gates = gates; CP.gates2 = gates2;
    CP.hsc = hsc; CP.h_out = h_out; CP.c_out = c_out;
    fused_chain<<<128, 128>>>(CP);

    // ---- launch 4: logits on the fat async core (hsc pre-rounded -> aRd=1) ----
    GemmList L5; L5.n = 1;
    L5.g[0] = mkgrp(hsc, 1024, W_out, 1024, b_out, logits, 20000, 128, 20000, 1024, 0, 1, 0);
    gemm_async_grouped<<<L5.g[0].end, 128>>>(L5);
}

// round 14
// speedup vs baseline: 1.0463x; 1.0463x over previous
#include <cuda_runtime.h>
#include <cstdint>

// ---------------------------------------------------------------------------
// Problem constants
//   B=128, T_V=64, T_A=128, E_V=1024, E_A=512, H=1024, EMB=512, C=512
//   IN=1024, VOCAB=20000
// Output = [logits(128*20000) | h_new(128*1024) | c_new(128*1024)]
// ---------------------------------------------------------------------------

// Scratch offsets (floats)
#define OFF_V2V     0u            // 8192*512
#define OFF_V2A     4194304u      // 16384*512
#define OFF_V1V     12582912u     // 128*512
#define OFF_V1A     12648448u     // 128*512
#define OFF_V1C     12713984u     // 128*512
#define OFF_CTXV    12779520u     // 128*1024
#define OFF_CTXA    12910592u     // 128*512
#define OFF_ALLCTX  12976128u     // 128*2*512
#define OFF_V2C     13107200u     // 256*512
#define OFF_X2      13238272u     // 128*512
#define OFF_GATES   13369344u     // 128*4096
#define OFF_H       13893632u     // 128*1024
#define OFF_VTMP    14024704u     // 128*512
#define OFF_V2CTMP  14090240u     // 256*512
#define OFF_GATES2  14221312u     // 128*4096
#define SCRATCH_FLOATS 14745600u

__device__ float g_scratch[SCRATCH_FLOATS];
__device__ int g_bar[8];   // monotonic barrier counters (never reset; replay-safe)

__device__ __forceinline__ uint32_t f2tf(float f) {
    uint32_t u;
    asm("cvt.rna.tf32.f32 %0, %1;" : "=r"(u) : "f"(f));
    return u;
}
__device__ __forceinline__ float f2tf_f(float f) {
    return __uint_as_float(f2tf(f));
}

// Grid-wide barrier for a co-resident grid of nblk blocks. Tight spin.
__device__ __forceinline__ void grid_bar(int i, int nblk) {
    __syncthreads();
    if (threadIdx.x == 0) {
        __threadfence();
        int old = atomicAdd(&g_bar[i], 1);
        int goal = (old / nblk + 1) * nblk;
        volatile int* p = &g_bar[i];
        while (*p < goal) { }
        __threadfence();
    }
    __syncthreads();
}

// ---------------------------------------------------------------------------
// Async TF32 core, FAT tile: 128(M) x 64(N) x 32(K), 128 threads, 4 warps
// as 2x2, warp tile 64x32. cp.async 2-stage + XOR-swizzled smem + ldmatrix.
// ARD (compile-time): A operand already tf32-rna-rounded by its producer ->
// skip A cvt (bitwise-identical numerics; rounding applied exactly once).
// ARD=0 instantiation is byte-identical to the proven R11 core.
// M%128==0, K%32==0, lda/ldb%4==0. N ragged OK (B rows clamped; epilogue
// guarded).
// smem sm[12288] uint32 = 48KB:
//   A stage0 @ byte 0, A stage1 @ 16384 ; B stage0 @ 32768, B stage1 @ 40960.
//   Row r: 16B group g stored at physical group g ^ (r & 7).
// ---------------------------------------------------------------------------
__device__ __forceinline__ void cp16(uint32_t dst, const float* src) {
    asm volatile("cp.async.ca.shared.global [%0], [%1], 16;"
                 :: "r"(dst), "l"(src));
}
__device__ __forceinline__ void cp_commit() {
    asm volatile("cp.async.commit_group;");
}
__device__ __forceinline__ void ldsm4(uint32_t* r, uint32_t addr) {
    asm volatile("ldmatrix.sync.aligned.m8n8.x4.shared.b16 {%0,%1,%2,%3}, [%4];"
                 : "=r"(r[0]), "=r"(r[1]), "=r"(r[2]), "=r"(r[3]) : "r"(addr));
}

template<int ARD>
__device__ __forceinline__ void gemm_async_core(
    const float* __restrict__ A, int lda,
    const float* __restrict__ B, int ldb,
    const float* __restrict__ bias,
    float* __restrict__ C, int ldc,
    int N, int K, int accum, int mBase, int nBase,
    uint32_t* sm)
{
    const int tid  = threadIdx.x;
    const int lane = tid & 31;
    const int warp = tid >> 5;
    const int wm = warp >> 1;
    const int wn = warp & 1;
    const int lr = tid >> 3;
    const int lc = tid & 7;
    const int nk = K >> 5;

    const uint32_t smBase = (uint32_t)__cvta_generic_to_shared(sm);
    const int sg = lc ^ (lr & 7);
    const float* aS0 = A + (size_t)(mBase + lr) * lda + (lc << 2);
    const size_t strideA16 = (size_t)16 * lda;
    const float* bS[4];
#pragma unroll
    for (int i = 0; i < 4; i++) {
        int nr = nBase + lr + i * 16;
        if (nr > N - 1) nr = N - 1;
        bS[i] = B + (size_t)nr * ldb + (lc << 2);
    }
    const uint32_t aD = smBase + lr * 128 + sg * 16;
    const uint32_t bD = smBase + 32768 + lr * 128 + sg * 16;

    auto issue = [&](int kt, int st) {
        const int ko = kt << 5;
        const uint32_t soA = st ? 16384u : 0u;
        const uint32_t soB = st ? 8192u : 0u;
#pragma unroll
        for (int i = 0; i < 8; i++)
            cp16(aD + (uint32_t)i * 2048u + soA, aS0 + (size_t)i * strideA16 + ko);
#pragma unroll
        for (int i = 0; i < 4; i++)
            cp16(bD + (uint32_t)i * 2048u + soB, bS[i] + ko);
        cp_commit();
    };

    float acc[4][4][4];
#pragma unroll
    for (int i = 0; i < 4; i++)
#pragma unroll
        for (int j = 0; j < 4; j++)
#pragma unroll
            for (int k = 0; k < 4; k++) acc[i][j][k] = 0.f;

    issue(0, 0);
    if (nk > 1) issue(1, 1);

    const int l7 = lane & 7;
    const int q3 = (lane >> 3) & 1;
    const int q4 = (lane >> 4) & 1;
    const uint32_t aAB = smBase + ((wm << 6) + l7 + (q3 << 3)) * 128;
    const uint32_t bAB = smBase + 32768 + ((wn << 5) + l7 + (q4 << 3)) * 128;

    for (int kt = 0; kt < nk; kt++) {
        if (kt < nk - 1) asm volatile("cp.async.wait_group 1;");
        else             asm volatile("cp.async.wait_group 0;");
        __syncthreads();

        const int st = kt & 1;
        const uint32_t swA = st ? 16384u : 0u;
        const uint32_t swB = st ? 8192u : 0u;
#pragma unroll
        for (int kk = 0; kk < 32; kk += 8) {
            const int kk4 = kk >> 2;
            uint32_t am[4][4], bm[2][4];
            const uint32_t ag = (uint32_t)((kk4 + q4) ^ l7);
            const uint32_t aaddr = aAB + swA + ag * 16;
            ldsm4(am[0], aaddr);
            ldsm4(am[1], aaddr + 2048);
            ldsm4(am[2], aaddr + 4096);
            ldsm4(am[3], aaddr + 6144);
            const uint32_t bg = (uint32_t)((kk4 + q3) ^ l7);
            const uint32_t baddr = bAB + swB + bg * 16;
            ldsm4(bm[0], baddr);
            ldsm4(bm[1], baddr + 2048);

            if (ARD == 0) {
#pragma unroll
                for (int im = 0; im < 4; im++)
#pragma unroll
                    for (int j = 0; j < 4; j++)
                        am[im][j] = f2tf(__uint_as_float(am[im][j]));
            }
#pragma unroll
            for (int p = 0; p < 2; p++)
#pragma unroll
                for (int j = 0; j < 4; j++)
                    bm[p][j] = f2tf(__uint_as_float(bm[p][j]));

#pragma unroll
            for (int im = 0; im < 4; im++)
#pragma unroll
                for (int jn = 0; jn < 4; jn++) {
                    const uint32_t b0 = bm[jn >> 1][(jn & 1) << 1];
                    const uint32_t b1 = bm[jn >> 1][((jn & 1) << 1) + 1];
                    asm volatile(
                        "mma.sync.aligned.m16n8k8.row.col.f32.tf32.tf32.f32 "
                        "{%0,%1,%2,%3}, {%4,%5,%6,%7}, {%8,%9}, {%0,%1,%2,%3};"
                        : "+f"(acc[im][jn][0]), "+f"(acc[im][jn][1]),
                          "+f"(acc[im][jn][2]), "+f"(acc[im][jn][3])
                        : "r"(am[im][0]), "r"(am[im][1]), "r"(am[im][2]), "r"(am[im][3]),
                          "r"(b0), "r"(b1));
                }
        }

        __syncthreads();
        if (kt + 2 < nk) issue(kt + 2, kt & 1);
    }

#pragma unroll
    for (int im = 0; im < 4; im++) {
        const int m0 = mBase + (wm << 6) + (im << 4) + (lane >> 2);
#pragma unroll
        for (int jn = 0; jn < 4; jn++) {
            const int n0 = nBase + (wn << 5) + (jn << 3) + ((lane & 3) << 1);
#pragma unroll
            for (int half = 0; half < 2; half++) {
                const int m = m0 + half * 8;
                const float v0 = acc[im][jn][half * 2 + 0];
                const float v1 = acc[im][jn][half * 2 + 1];
                if (n0 < N) {
                    float xv = v0 + (bias ? bias[n0] : 0.f);
                    if (accum) C[(size_t)m * ldc + n0] += xv;
                    else       C[(size_t)m * ldc + n0]  = xv;
                }
                if (n0 + 1 < N) {
                    float xv = v1 + (bias ? bias[n0 + 1] : 0.f);
                    if (accum) C[(size_t)m * ldc + n0 + 1] += xv;
                    else       C[(size_t)m * ldc + n0 + 1]  = xv;
                }
            }
        }
    }
}

struct GemmGroup {
    const float* A; const float* B; const float* bias; float* C;
    int lda, ldb, ldc, N, K, accum, nbx, end;
};
struct GemmList { GemmGroup g[8]; int n; };

template<int ARD>
__global__ void __launch_bounds__(128) gemm_async_grouped(GemmList L)
{
    __shared__ uint32_t sm[12288];   // 48KB exactly

    const int bid = blockIdx.x;
    int gi = 0;
#pragma unroll
    for (int i = 0; i < 8; i++)
        if (i < L.n && bid >= L.g[i].end) gi = i + 1;
    const GemmGroup& G = L.g[gi];
    const int start = gi ? L.g[gi - 1].end : 0;
    const int lb = bid - start;
    const int by = lb / G.nbx;
    const int bx = lb - by * G.nbx;

    gemm_async_core<ARD>(G.A, G.lda, G.B, G.ldb, G.bias, G.C, G.ldc,
                         G.N, G.K, G.accum, by << 7, bx << 6, sm);
}

// ---------------------------------------------------------------------------
// Both Bahdanau attentions in one launch. ctx written tf32-rna-rounded
// (consumed ONLY as GEMM A-operand in the chain -> bitwise-identical).
// ---------------------------------------------------------------------------
struct AttParams {
    const float* v1; const float* v2; const float* W3; const float* enc;
    float* ctx; int T, C, E;
};

__global__ void __launch_bounds__(256) attend_both(AttParams P0, AttParams P1)
{
    const AttParams P = (blockIdx.x >> 7) ? P1 : P0;
    const int b = blockIdx.x & 127;
    const int tid = threadIdx.x;
    const int warp = tid >> 5, lane = tid & 31;
    __shared__ float s_sc[128];
    __shared__ float s_inv;

    const int T = P.T, C = P.C, E = P.E;
    const float* v1b = P.v1 + (size_t)b * C;
    const float* v2b = P.v2 + (size_t)b * T * C;

    for (int t = warp; t < T; t += 8) {
        const float* row = v2b + (size_t)t * C;
        float acc = 0.f;
        for (int c = lane; c < C; c += 32)
            acc += tanhf(v1b[c] + row[c]) * P.W3[c];
#pragma unroll
        for (int o = 16; o; o >>= 1) acc += __shfl_xor_sync(0xffffffffu, acc, o);
        if (lane == 0) s_sc[t] = acc;
    }
    __syncthreads();

    if (tid == 0) {
        float m = -1e30f;
        for (int t = 0; t < T; t++) m = fmaxf(m, s_sc[t]);
        float s = 0.f;
        for (int t = 0; t < T; t++) { float e = expf(s_sc[t] - m); s_sc[t] = e; s += e; }
        s_inv = 1.f / s;
    }
    __syncthreads();
    const float inv = s_inv;

    const float* encb = P.enc + (size_t)b * T * E;
    for (int e = tid; e < E; e += 256) {
        float acc = 0.f;
        for (int t = 0; t < T; t++) acc += s_sc[t] * encb[(size_t)t * E + e];
        P.ctx[(size_t)b * E + e] = f2tf_f(acc * inv);
    }
}

// ---------------------------------------------------------------------------
// Persistent fused chain with split-K parallelism (128x64 tile tasks).
// Grid MUST be 128 blocks x 128 threads (co-resident; tight-spin barriers).
// ---------------------------------------------------------------------------
struct ChainParams {
    const float* ctxv; const float* ctxa;
    const float* W_venc; const float* W_aenc; const float* W_ca2;
    const float* v1c; const float* W_ca3; const float* W_ih;
    const float* b_ih; const float* b_hh; const float* c0;
    float* allctx; float* vtmp; float* v2c; float* v2ctmp;
    float* x2; float* gates; const float* gates2;
    float* hsc; float* h_out; float* c_out;
};

__global__ void __launch_bounds__(128) fused_chain(ChainParams P)
{
    __shared__ uint32_t sm[12288];
    float* redf = (float*)sm;

    const int bid = blockIdx.x;
    const int tid = threadIdx.x;

    // ---- P1: proj (A = ctx, pre-rounded -> ARD=1) ----
    if (bid < 24) {
        if (bid < 8) {
            gemm_async_core<1>(P.ctxv, 1024, P.W_venc, 1024, nullptr, P.allctx, 1024,
                               512, 512, 0, 0, bid << 6, sm);
        } else if (bid < 16) {
            const int t = bid - 8;
            gemm_async_core<1>(P.ctxv + 512, 1024, P.W_venc + 512, 1024, nullptr,
                               P.vtmp, 512, 512, 512, 0, 0, t << 6, sm);
        } else {
            const int t = bid - 16;
            gemm_async_core<1>(P.ctxa, 512, P.W_aenc, 512, nullptr, P.allctx + 512, 1024,
                               512, 512, 0, 0, t << 6, sm);
        }
    }
    grid_bar(0, 128);

    // ---- P1b: reduce vis partials into allctx ----
    for (int u = bid * 128 + tid; u < 128 * 512; u += 128 * 128) {
        const int b = u >> 9, c = u & 511;
        P.allctx[(size_t)b * 1024 + c] += P.vtmp[u];
    }
    grid_bar(1, 128);

    // ---- P2: v2c[256,512] = allctx @ W_ca2^T, split-K=2 (A raw -> ARD=0) ----
    if (bid < 32) {
        const int kc = bid >> 4;
        const int t = bid & 15;
        const float* Aa = P.allctx + kc * 256;
        const float* Bb = P.W_ca2 + kc * 256;
        float* Cc = kc ? P.v2ctmp : P.v2c;
        gemm_async_core<0>(Aa, 512, Bb, 512, nullptr, Cc, 512,
                           512, 256, 0, (t >> 3) << 7, (t & 7) << 6, sm);
    }
    grid_bar(2, 128);

    // ---- P3: 2-way softmax + final ctx + x2 = tf32(tanh(final_ctx)) ----
    {
        const int b = bid;
        const int warp = tid >> 5, lane = tid & 31;
        const float* v1b  = P.v1c + (size_t)b * 512;
        const float* v20  = P.v2c + (size_t)(2 * b) * 512;
        const float* v21  = v20 + 512;
        const float* v20t = P.v2ctmp + (size_t)(2 * b) * 512;
        const float* v21t = v20t + 512;

        float p0 = 0.f, p1 = 0.f;
        for (int c = tid; c < 512; c += 128) {
            const float w = P.W_ca3[c];
            p0 += tanhf(v1b[c] + v20[c] + v20t[c]) * w;
            p1 += tanhf(v1b[c] + v21[c] + v21t[c]) * w;
        }
#pragma unroll
        for (int o = 16; o; o >>= 1) {
            p0 += __shfl_xor_sync(0xffffffffu, p0, o);
            p1 += __shfl_xor_sync(0xffffffffu, p1, o);
        }
        if (lane == 0) { redf[warp] = p0; redf[4 + warp] = p1; }
        __syncthreads();
        if (tid == 0) {
            float s0 = redf[0] + redf[1] + redf[2] + redf[3];
            float s1 = redf[4] + redf[5] + redf[6] + redf[7];
            const float m = fmaxf(s0, s1);
            const float e0 = expf(s0 - m), e1 = expf(s1 - m);
            const float inv = 1.f / (e0 + e1);
            redf[8] = e0 * inv; redf[9] = e1 * inv;
        }
        __syncthreads();
        const float a0 = redf[8], a1 = redf[9];

        const float* ctx0 = P.allctx + (size_t)b * 1024;
        const float* ctx1 = ctx0 + 512;
        float* xb = P.x2 + (size_t)b * 512;
        for (int c = tid; c < 512; c += 128)
            xb[c] = f2tf_f(tanhf(a0 * ctx0[c] + a1 * ctx1[c]));
        __syncthreads();
    }
    grid_bar(3, 128);

    // ---- P4: gates += x2 @ W_ih[:,512:]^T (x2 pre-rounded -> ARD=1) ----
    if (bid < 64) {
        gemm_async_core<1>(P.x2, 512, P.W_ih + 512, 1024, nullptr, P.gates, 4096,
                           4096, 512, 1, 0, bid << 6, sm);
    }
    grid_bar(4, 128);

    // ---- P5: LSTM pointwise; hsc stored tf32-rounded (logits A operand) ----
    for (int idx = bid * 128 + tid; idx < 128 * 1024; idx += 128 * 128) {
        const int b = idx >> 10, k = idx & 1023;
        const float* g  = P.gates  + (size_t)b * 4096;
        const float* g2 = P.gates2 + (size_t)b * 4096;
        const float ig = g[k]        + g2[k]        + P.b_ih[k]        + P.b_hh[k];
        const float fg = g[1024 + k] + g2[1024 + k] + P.b_ih[1024 + k] + P.b_hh[1024 + k];
        const float gg = g[2048 + k] + g2[2048 + k] + P.b_ih[2048 + k] + P.b_hh[2048 + k];
        const float og = g[3072 + k] + g2[3072 + k] + P.b_ih[3072 + k] + P.b_hh[3072 + k];

        const float si = 1.f / (1.f + expf(-ig));
        const float sf = 1.f / (1.f + expf(-fg));
        const float so = 1.f / (1.f + expf(-og));
        const float cn = sf * P.c0[idx] + si * tanhf(gg);
        const float hn = so * tanhf(cn);

        P.hsc[idx] = f2tf_f(hn);
        P.h_out[idx] = hn;
        P.c_out[idx] = cn;
    }
}

// ---------------------------------------------------------------------------
// Launch
// ---------------------------------------------------------------------------
static inline GemmGroup mkgrp(const float* A, int lda, const float* B, int ldb,
                              const float* bias, float* C, int ldc,
                              int M, int N, int K, int accum, int prevEnd)
{
    GemmGroup g;
    g.A = A; g.B = B; g.bias = bias; g.C = C;
    g.lda = lda; g.ldb = ldb; g.ldc = ldc;
    g.N = N; g.K = K; g.accum = accum;
    g.nbx = (N + 63) / 64;
    g.end = prevEnd + g.nbx * (M / 128);
    return g;
}

extern "C" void kernel_launch(void* const* d_in, const int* in_sizes, int n_in,
                              void* d_out, int out_size)
{
    (void)in_sizes; (void)n_in; (void)out_size;

    float* S = nullptr;
    cudaGetSymbolAddress((void**)&S, g_scratch);

    const float* input  = (const float*)d_in[0];
    const float* enc_v  = (const float*)d_in[1];
    const float* enc_a  = (const float*)d_in[2];
    const float* h0     = (const float*)d_in[3];
    const float* c0     = (const float*)d_in[4];
    const float* W_va1  = (const float*)d_in[5];
    const float* W_va2  = (const float*)d_in[6];
    const float* W_va3  = (const float*)d_in[7];
    const float* W_venc = (const float*)d_in[8];
    const float* W_aa1  = (const float*)d_in[9];
    const float* W_aa2  = (const float*)d_in[10];
    const float* W_aa3  = (const float*)d_in[11];
    const float* W_aenc = (const float*)d_in[12];
    const float* W_ca1  = (const float*)d_in[13];
    const float* W_ca2  = (const float*)d_in[14];
    const float* W_ca3  = (const float*)d_in[15];
    const float* W_ih   = (const float*)d_in[16];
    const float* W_hh   = (const float*)d_in[17];
    const float* b_ih   = (const float*)d_in[18];
    const float* b_hh   = (const float*)d_in[19];
    const float* W_out  = (const float*)d_in[20];
    const float* b_out  = (const float*)d_in[21];

    float* out    = (float*)d_out;
    float* logits = out;
    float* h_out  = out + 128 * 20000;
    float* c_out  = h_out + 128 * 1024;

    float* v2v    = S + OFF_V2V;
    float* v2a    = S + OFF_V2A;
    float* v1v    = S + OFF_V1V;
    float* v1a    = S + OFF_V1A;
    float* v1c    = S + OFF_V1C;
    float* ctxv   = S + OFF_CTXV;
    float* ctxa   = S + OFF_CTXA;
    float* allctx = S + OFF_ALLCTX;
    float* v2c    = S + OFF_V2C;
    float* x2     = S + OFF_X2;
    float* gates  = S + OFF_GATES;
    float* hsc    = S + OFF_H;
    float* vtmp   = S + OFF_VTMP;
    float* v2ctmp = S + OFF_V2CTMP;
    float* gates2 = S + OFF_GATES2;

    // ---- launch 1: input-only GEMMs (ARD=0 core, identical to R11) ----
    GemmList L1; L1.n = 7;
    L1.g[0] = mkgrp(enc_a, 512,  W_aa2, 512,  nullptr, v2a,    512,  16384, 512,  512,  0, 0);
    L1.g[1] = mkgrp(enc_v, 1024, W_va2, 1024, nullptr, v2v,    512,  8192,  512,  1024, 0, L1.g[0].end);
    L1.g[2] = mkgrp(h0,    1024, W_hh,  1024, nullptr, gates,  4096, 128,   4096, 1024, 0, L1.g[1].end);
    L1.g[3] = mkgrp(input, 512,  W_ih,  1024, nullptr, gates2, 4096, 128,   4096, 512,  0, L1.g[2].end);
    L1.g[4] = mkgrp(h0,    1024, W_va1, 1024, nullptr, v1v,    512,  128,   512,  1024, 0, L1.g[3].end);
    L1.g[5] = mkgrp(h0,    1024, W_aa1, 1024, nullptr, v1a,    512,  128,   512,  1024, 0, L1.g[4].end);
    L1.g[6] = mkgrp(h0,    1024, W_ca1, 1024, nullptr, v1c,    512,  128,   512,  1024, 0, L1.g[5].end);
    gemm_async_grouped<0><<<L1.g[6].end, 128>>>(L1);

    // ---- launch 2: both attentions (ctx written tf32-rounded) ----
    AttParams Pv{v1v, v2v, W_va3, enc_v, ctxv, 64, 512, 1024};
    AttParams Pa{v1a, v2a, W_aa3, enc_a, ctxa, 128, 512, 512};
    attend_both<<<256, 256>>>(Pv, Pa);

    // ---- launch 3: persistent fused chain ----
    ChainParams CP;
    CP.ctxv = ctxv; CP.ctxa = ctxa;
    CP.W_venc = W_venc; CP.W_aenc = W_aenc; CP.W_ca2 = W_ca2;
    CP.v1c = v1c; CP.W_ca3 = W_ca3; CP.W_ih = W_ih;
    CP.b_ih = b_ih; CP.b_hh = b_hh; CP.c0 = c0;
    CP.allctx = allctx; CP.vtmp = vtmp; CP.v2c = v2c; CP.v2ctmp = v2ctmp;
    CP.x2 = x2; CP.gates = gates; CP.gates2 = gates2;
    CP.hsc = hsc; CP.h_out = h_out; CP.c_out = c_out;
    fused_chain<<<128, 128>>>(CP);

    // ---- launch 4: logits (hsc pre-rounded -> ARD=1 core) ----
    GemmList L5; L5.n = 1;
    L5.g[0] = mkgrp(hsc, 1024, W_out, 1024, b_out, logits, 20000, 128, 20000, 1024, 0, 0);
    gemm_async_grouped<1><<<L5.g[0].end, 128>>>(L5);
}